// round 4
// baseline (speedup 1.0000x reference)
#include <cuda_runtime.h>
#include <cstdint>

#define B_  4
#define C_  256
#define H_  96
#define W_  128
#define P_  9
#define HW_ (H_ * W_)
#define CHW_ (C_ * H_ * W_)

#define TX  32           // x pixels per block
#define TY  4            // y pixels per block
#define PT  4            // x pixels per thread
#define XG  8            // TX/PT
#define THREADS 288      // XG * 9 * TY
#define CC  8            // channels per stage
#define NSTAGE (C_ / CC) // 32
#define HALO_WP 44       // padded halo row stride (floats), conflict-free
#define HALO_H  12

#define S2F (CC * HALO_H * HALO_WP)   // 4224 floats per buffer
#define S2B (S2F * 4)                 // 16896 bytes
#define GSTAGEB (CC * HW_ * 4)        // gmem bytes per stage slab

#define N_LD  960                     // in2 float4 chunks per stage (8ch x 12r x 10)

#define FLAG_OOB (1u << 26)

typedef unsigned long long u64;

__device__ __forceinline__ void cp_async16(uint32_t dst, const void* src, int srcsize) {
    asm volatile("cp.async.cg.shared.global [%0], [%1], 16, %2;\n"
                 :: "r"(dst), "l"(src), "r"(srcsize));
}
__device__ __forceinline__ void cp_commit() {
    asm volatile("cp.async.commit_group;\n" ::: "memory");
}
template <int N>
__device__ __forceinline__ void cp_wait() {
    asm volatile("cp.async.wait_group %0;\n" :: "n"(N) : "memory");
}

__device__ __forceinline__ u64 pk2(float lo, float hi) {
    u64 r;
    asm("mov.b64 %0, {%1, %2};" : "=l"(r) : "f"(lo), "f"(hi));
    return r;
}
// packed dual-FMA on fma pipe (FFMA2): d.lo += a.lo*b.lo ; d.hi += a.hi*b.hi
__device__ __forceinline__ void fma2(u64& d, u64 a, u64 b) {
    asm("fma.rn.f32x2 %0, %1, %2, %0;" : "+l"(d) : "l"(a), "l"(b));
}
__device__ __forceinline__ void unpk2(float& lo, float& hi, u64 v) {
    asm("mov.b64 {%0, %1}, %2;" : "=f"(lo), "=f"(hi) : "l"(v));
}

__global__ void __launch_bounds__(THREADS, 3)
corr_kernel(const float* __restrict__ in1,
            const float* __restrict__ in2,
            float* __restrict__ out)
{
    __shared__ __align__(16) float    sbuf[2][S2F];   // in2 halo, double buffered
    __shared__             uint32_t   desc[N_LD];     // packed cp.async descriptors

    const int tid = threadIdx.x;
    const int b   = blockIdx.z;
    const int y0  = blockIdx.y * TY;
    const int x0  = blockIdx.x * TX;

    const char* g2 = (const char*)(in2 + (size_t)b * CHW_);

    const uint32_t sbase = (uint32_t)__cvta_generic_to_shared(&sbuf[0][0]);

    // ---- build packed descriptor table for in2 halo (once per block) ----
    for (int i = tid; i < N_LD; i += THREADS) {
        // 120 chunks per channel: 12 rows x 10 float4, padded row stride 44
        int cc = i / 120;
        int r  = i - cc * 120;
        int ry = r / 10;
        int j  = r - ry * 10;
        uint32_t soff = (uint32_t)(((cc * HALO_H + ry) * HALO_WP + 4 * j) * 4);
        int gy = y0 + ry - 4;
        int gx = x0 + 4 * j - 4;
        bool oob = (gy < 0) || (gy >= H_) || (gx < 0) || (gx > W_ - 4);
        uint32_t goff = oob ? 0u : (uint32_t)(((cc * H_ + gy) * W_ + gx) * 4);
        desc[i] = (soff >> 4) | ((goff >> 4) << 11) | (oob ? FLAG_OOB : 0u);
    }

    // ---- compute-role decomposition: tid = (yy*9 + dy)*8 + g ----
    const int g   = tid & 7;          // x-group (0..7), 4 px each
    const int dy  = (tid >> 3) % 9;   // shift row (0..8)
    const int yy  = tid / 72;         // block-local output row (0..3)

    u64 acc2[PT / 2][P_];             // (x pair) x (dx) packed accumulators
    #pragma unroll
    for (int t = 0; t < PT / 2; t++)
        #pragma unroll
        for (int d = 0; d < P_; d++)
            acc2[t][d] = 0ull;

    const int w_off = (yy + dy) * HALO_WP + 4 * g;    // window base (buf 0, cc 0)
    // in1 read directly via LDG (L1-cached, warp-dedup'd across dy)
    const float* a_ptr = in1 + (size_t)b * CHW_ + (size_t)(y0 + yy) * W_ + x0 + 4 * g;

    __syncthreads();   // desc table ready

    // ---- prologue: issue stage 0 ----
    for (int i = tid; i < N_LD; i += THREADS) {
        uint32_t d = desc[i];
        cp_async16(sbase + ((d & 0x7FFu) << 4),
                   g2 + (((d >> 11) & 0x7FFFu) << 4),
                   (d & FLAG_OOB) ? 0 : 16);
    }
    cp_commit();

    for (int st = 0; st < NSTAGE; st++) {
        cp_wait<0>();      // stage st halo landed
        __syncthreads();   // all threads past compute st-1; safe to refill buf^1

        if (st + 1 < NSTAGE) {
            const uint32_t buf_add = (uint32_t)((st + 1) & 1) * S2B;
            const size_t   gadd    = (size_t)(st + 1) * GSTAGEB;
            for (int i = tid; i < N_LD; i += THREADS) {
                uint32_t d = desc[i];
                cp_async16(sbase + ((d & 0x7FFu) << 4) + buf_add,
                           g2 + ((((d >> 11) & 0x7FFFu) << 4) + gadd),
                           (d & FLAG_OOB) ? 0 : 16);
            }
            cp_commit();
        }

        const float* wp = &sbuf[st & 1][w_off];
        const float* ap = a_ptr + (size_t)st * CC * HW_;

        #pragma unroll 2
        for (int cc = 0; cc < CC; cc++) {
            const float4* wp4 = reinterpret_cast<const float4*>(wp);
            float4 w0 = wp4[0], w1 = wp4[1], w2 = wp4[2];
            float4 a  = __ldg(reinterpret_cast<const float4*>(ap));

            u64 av0 = pk2(a.x, a.y);
            u64 av1 = pk2(a.z, a.w);

            float wf[12];
            wf[0] = w0.x; wf[1]  = w0.y; wf[2]  = w0.z; wf[3]  = w0.w;
            wf[4] = w1.x; wf[5]  = w1.y; wf[6]  = w1.z; wf[7]  = w1.w;
            wf[8] = w2.x; wf[9]  = w2.y; wf[10] = w2.z; wf[11] = w2.w;

            u64 wq[11];
            #pragma unroll
            for (int k = 0; k < 11; k++)
                wq[k] = pk2(wf[k], wf[k + 1]);

            #pragma unroll
            for (int d = 0; d < P_; d++) {
                fma2(acc2[0][d], av0, wq[d]);
                fma2(acc2[1][d], av1, wq[d + 2]);
            }

            wp += HALO_H * HALO_WP;
            ap += HW_;
        }
        // no trailing syncthreads: next iteration's top barrier orders
        // this stage's reads before buf^1 is refilled (2-stage distance).
    }

    // ---- write output: out[b][dy][d][y0+yy][x0+4g .. +3] ----
    {
        const size_t hw = (size_t)HW_;
        float* obase = out + (((size_t)b * P_ + dy) * P_) * hw
                     + (size_t)(y0 + yy) * W_ + x0 + 4 * g;
        #pragma unroll
        for (int d = 0; d < P_; d++) {
            float4 v;
            unpk2(v.x, v.y, acc2[0][d]);
            unpk2(v.z, v.w, acc2[1][d]);
            *reinterpret_cast<float4*>(obase + (size_t)d * hw) = v;
        }
    }
}

extern "C" void kernel_launch(void* const* d_in, const int* in_sizes, int n_in,
                              void* d_out, int out_size) {
    const float* in1 = (const float*)d_in[0];
    const float* in2 = (const float*)d_in[1];
    float* out = (float*)d_out;

    dim3 grid(W_ / TX, H_ / TY, B_);   // (4, 24, 4) = 384 blocks
    dim3 block(THREADS);               // 288
    corr_kernel<<<grid, block>>>(in1, in2, out);
}

// round 5
// speedup vs baseline: 1.0434x; 1.0434x over previous
#include <cuda_runtime.h>
#include <cstdint>

#define B_  4
#define C_  256
#define H_  96
#define W_  128
#define P_  9
#define HW_ (H_ * W_)
#define CHW_ (C_ * H_ * W_)

#define TX  32           // x pixels per block
#define TY  4            // y pixels per block
#define PT  4            // x pixels per thread
#define THREADS 288      // (TX/PT) * 9 * TY
#define CC  8            // channels per stage
#define NSTAGE (C_ / CC) // 32
#define NBUF 3           // triple buffer, prefetch distance 2
#define HALO_WP 44       // padded halo row stride (floats), conflict-free
#define HALO_H  12

#define S1F (CC * TY * TX)            // 1024 floats (in1 tile)
#define S2F (CC * HALO_H * HALO_WP)   // 4224 floats (in2 halo)
#define STAGEF (S1F + S2F)            // 5248 floats
#define STAGEB (STAGEF * 4)           // 20992 bytes
#define GSTAGEB (CC * HW_ * 4)        // gmem bytes per channel-stage slab

#define N_LD1 256                     // in1 float4 chunks per stage
#define N_LD  1216                    // + 960 in2 halo chunks

#define FLAG_OOB (1u << 26)
#define FLAG_IN2 (1u << 27)

typedef unsigned long long u64;

__device__ __forceinline__ void cp_async16(uint32_t dst, const void* src, int srcsize) {
    asm volatile("cp.async.cg.shared.global [%0], [%1], 16, %2;\n"
                 :: "r"(dst), "l"(src), "r"(srcsize));
}
__device__ __forceinline__ void cp_commit() {
    asm volatile("cp.async.commit_group;\n" ::: "memory");
}
template <int N>
__device__ __forceinline__ void cp_wait() {
    asm volatile("cp.async.wait_group %0;\n" :: "n"(N) : "memory");
}

__device__ __forceinline__ u64 pk2(float lo, float hi) {
    u64 r;
    asm("mov.b64 %0, {%1, %2};" : "=l"(r) : "f"(lo), "f"(hi));
    return r;
}
// packed dual-FMA on fma pipe (FFMA2): d.lo += a.lo*b.lo ; d.hi += a.hi*b.hi
__device__ __forceinline__ void fma2(u64& d, u64 a, u64 b) {
    asm("fma.rn.f32x2 %0, %1, %2, %0;" : "+l"(d) : "l"(a), "l"(b));
}
__device__ __forceinline__ void unpk2(float& lo, float& hi, u64 v) {
    asm("mov.b64 {%0, %1}, %2;" : "=f"(lo), "=f"(hi) : "l"(v));
}

__global__ void __launch_bounds__(THREADS, 3)
corr_kernel(const float* __restrict__ in1,
            const float* __restrict__ in2,
            float* __restrict__ out)
{
    __shared__ __align__(16) float    sbuf[NBUF][STAGEF];  // [buf][ s1 | s2 halo ]
    __shared__             uint32_t   desc[N_LD];          // packed load descriptors

    const int tid = threadIdx.x;
    const int b   = blockIdx.z;
    const int y0  = blockIdx.y * TY;
    const int x0  = blockIdx.x * TX;

    const char* g1 = (const char*)(in1 + (size_t)b * CHW_);
    const char* g2 = (const char*)(in2 + (size_t)b * CHW_);

    const uint32_t sbase = (uint32_t)__cvta_generic_to_shared(&sbuf[0][0]);

    // ---- build packed descriptor table (once per block) ----
    for (int i = tid; i < N_LD; i += THREADS) {
        uint32_t soff, goff, flags = 0;
        if (i < N_LD1) {
            // in1 tile: 32 chunks per channel (4 rows x 8 float4)
            int cc = i >> 5;
            int r  = i & 31;
            int ry = r >> 3;
            int j  = r & 7;
            soff = (uint32_t)(((cc * TY + ry) * TX + 4 * j) * 4);
            goff = (uint32_t)(((cc * H_ + (y0 + ry)) * W_ + x0 + 4 * j) * 4);
        } else {
            // in2 halo: 120 chunks per channel (12 rows x 10 float4), padded rows
            int t  = i - N_LD1;
            int cc = t / 120;
            int r  = t - cc * 120;
            int ry = r / 10;
            int j  = r - ry * 10;
            soff = (uint32_t)(S1F * 4 + ((cc * HALO_H + ry) * HALO_WP + 4 * j) * 4);
            int gy = y0 + ry - 4;
            int gx = x0 + 4 * j - 4;
            bool oob = (gy < 0) || (gy >= H_) || (gx < 0) || (gx > W_ - 4);
            goff = oob ? 0u : (uint32_t)(((cc * H_ + gy) * W_ + gx) * 4);
            flags = FLAG_IN2 | (oob ? FLAG_OOB : 0u);
        }
        desc[i] = (soff >> 4) | ((goff >> 4) << 11) | flags;
    }

    // ---- compute roles: tid = (yy*9 + dy)*8 + g ----
    const int g   = tid & 7;          // x-group (0..7), 4 px each
    const int dy  = (tid >> 3) % 9;   // shift row (0..8)
    const int yy  = tid / 72;         // block-local output row (0..3)

    u64 acc2[PT / 2][P_];
    #pragma unroll
    for (int t = 0; t < PT / 2; t++)
        #pragma unroll
        for (int d = 0; d < P_; d++)
            acc2[t][d] = 0ull;

    const int w_off = S1F + (yy + dy) * HALO_WP + 4 * g;  // window base (buf 0, cc 0)
    const int a_off = yy * TX + 4 * g;                    // in1 base

    __syncthreads();   // desc table ready

    // ---- prologue: issue stages 0 and 1 ----
    #pragma unroll 1
    for (int ps = 0; ps < 2; ps++) {
        const uint32_t buf_add = (uint32_t)ps * STAGEB;
        const size_t   gadd    = (size_t)ps * GSTAGEB;
        for (int i = tid; i < N_LD; i += THREADS) {
            uint32_t d = desc[i];
            uint32_t soff = (d & 0x7FFu) << 4;
            const char* src = ((d & FLAG_IN2) ? g2 : g1)
                            + ((((d >> 11) & 0x7FFFu) << 4) + gadd);
            cp_async16(sbase + soff + buf_add, src, (d & FLAG_OOB) ? 0 : 16);
        }
        cp_commit();
    }

    #pragma unroll 1
    for (int st = 0; st < NSTAGE; st++) {
        // steady state: leave the distance-2 prefetch group in flight
        if (st < NSTAGE - 2) cp_wait<1>(); else cp_wait<0>();
        __syncthreads();   // stage st visible to all; compute of st-1 finished,
                           // so buf (st+2)%3 is free to refill

        if (st + 2 < NSTAGE) {
            const uint32_t buf_add = (uint32_t)((st + 2) % NBUF) * STAGEB;
            const size_t   gadd    = (size_t)(st + 2) * GSTAGEB;
            for (int i = tid; i < N_LD; i += THREADS) {
                uint32_t d = desc[i];
                uint32_t soff = (d & 0x7FFu) << 4;
                const char* src = ((d & FLAG_IN2) ? g2 : g1)
                                + ((((d >> 11) & 0x7FFFu) << 4) + gadd);
                cp_async16(sbase + soff + buf_add, src, (d & FLAG_OOB) ? 0 : 16);
            }
            cp_commit();
        }

        const int base = (st % NBUF) * STAGEF;
        const float* wp = &sbuf[0][base + w_off];
        const float* ap = &sbuf[0][base + a_off];

        #pragma unroll 2
        for (int cc = 0; cc < CC; cc++) {
            const float4* wp4 = reinterpret_cast<const float4*>(wp);
            float4 w0 = wp4[0], w1 = wp4[1], w2 = wp4[2];
            float4 a  = *reinterpret_cast<const float4*>(ap);

            u64 av0 = pk2(a.x, a.y);
            u64 av1 = pk2(a.z, a.w);

            float wf[12];
            wf[0] = w0.x; wf[1]  = w0.y; wf[2]  = w0.z; wf[3]  = w0.w;
            wf[4] = w1.x; wf[5]  = w1.y; wf[6]  = w1.z; wf[7]  = w1.w;
            wf[8] = w2.x; wf[9]  = w2.y; wf[10] = w2.z; wf[11] = w2.w;

            u64 wq[11];
            #pragma unroll
            for (int k = 0; k < 11; k++)
                wq[k] = pk2(wf[k], wf[k + 1]);

            #pragma unroll
            for (int d = 0; d < P_; d++) {
                fma2(acc2[0][d], av0, wq[d]);
                fma2(acc2[1][d], av1, wq[d + 2]);
            }

            wp += HALO_H * HALO_WP;
            ap += TY * TX;
        }
        // next iteration's top barrier orders this stage's reads before
        // its buffer is refilled (distance-2 reuse).
    }

    // ---- write output: out[b][dy][d][y0+yy][x0+4g .. +3] ----
    {
        const size_t hw = (size_t)HW_;
        float* obase = out + (((size_t)b * P_ + dy) * P_) * hw
                     + (size_t)(y0 + yy) * W_ + x0 + 4 * g;
        #pragma unroll
        for (int d = 0; d < P_; d++) {
            float4 v;
            unpk2(v.x, v.y, acc2[0][d]);
            unpk2(v.z, v.w, acc2[1][d]);
            *reinterpret_cast<float4*>(obase + (size_t)d * hw) = v;
        }
    }
}

extern "C" void kernel_launch(void* const* d_in, const int* in_sizes, int n_in,
                              void* d_out, int out_size) {
    const float* in1 = (const float*)d_in[0];
    const float* in2 = (const float*)d_in[1];
    float* out = (float*)d_out;

    dim3 grid(W_ / TX, H_ / TY, B_);   // (4, 24, 4) = 384 blocks
    dim3 block(THREADS);               // 288
    corr_kernel<<<grid, block>>>(in1, in2, out);
}

// round 8
// speedup vs baseline: 1.2145x; 1.1639x over previous
#include <cuda.h>
#include <cuda_runtime.h>
#include <cstdint>
#include <dlfcn.h>

#define B_  4
#define C_  256
#define H_  96
#define W_  128
#define P_  9
#define HW_ (H_ * W_)
#define CHW_ (C_ * H_ * W_)

#define TX  32           // x pixels per block
#define TY  4            // y pixels per block
#define PT  4            // x pixels per thread
#define THREADS 288      // (TX/PT) * 9 * TY
#define CC  8            // channels per stage
#define NSTAGE (C_ / CC) // 32
#define NBUF 3           // triple buffer, prefetch distance 2
#define HALO_W  40       // halo row width (floats); 160B rows
#define HALO_H  12

#define S2F_PER (CC * HALO_H * HALO_W)   // 3840 floats / buffer
#define S1F_PER (CC * TY * TX)           // 1024 floats / buffer
#define S2B_PER (S2F_PER * 4)            // 15360 B
#define S1B_PER (S1F_PER * 4)            // 4096 B
#define TX_BYTES ((uint32_t)(S1B_PER + S2B_PER))  // 19456 per stage (OOB fill counts)

typedef unsigned long long u64;

// ---- mbarrier primitives (proven forms from ptx_helpers / test_tma) ----
__device__ __forceinline__ void mbar_init(uint32_t mbar, uint32_t cnt) {
    asm volatile("mbarrier.init.shared.b64 [%0], %1;" :: "r"(mbar), "r"(cnt) : "memory");
}
__device__ __forceinline__ void mbar_expect_tx(uint32_t mbar, uint32_t tx) {
    asm volatile("mbarrier.arrive.expect_tx.shared.b64 _, [%0], %1;"
                 :: "r"(mbar), "r"(tx) : "memory");
}
__device__ __forceinline__ void mbar_wait(uint32_t mbar, uint32_t parity) {
    uint32_t done;
    asm volatile(
        "{\n\t"
        ".reg .pred p;\n\t"
        "mbarrier.try_wait.parity.acquire.cta.shared::cta.b64 p, [%1], %2;\n\t"
        "selp.b32 %0, 1, 0, p;\n\t"
        "}"
        : "=r"(done) : "r"(mbar), "r"(parity) : "memory");
    if (!done) {
        asm volatile(
            "{\n\t"
            ".reg .pred P1;\n\t"
            "WAIT_LOOP_%=:\n\t"
            "mbarrier.try_wait.parity.acquire.cta.shared::cta.b64 P1, [%0], %1, 0x989680;\n\t"
            "@P1 bra.uni WAIT_DONE_%=;\n\t"
            "bra.uni WAIT_LOOP_%=;\n\t"
            "WAIT_DONE_%=:\n\t"
            "}"
            :: "r"(mbar), "r"(parity) : "memory");
    }
}
__device__ __forceinline__ void tma4d(uint32_t dst, const CUtensorMap* m,
                                      int x, int y, int z, int w, uint32_t mbar) {
    asm volatile(
        "cp.async.bulk.tensor.4d.shared::cta.global.tile.mbarrier::complete_tx::bytes "
        "[%0], [%1, {%2, %3, %4, %5}], [%6];"
        :: "r"(dst), "l"(m), "r"(x), "r"(y), "r"(z), "r"(w), "r"(mbar) : "memory");
}
__device__ __forceinline__ void fence_async_shared() {
    asm volatile("fence.proxy.async.shared::cta;" ::: "memory");
}

// ---- packed fp32 math ----
__device__ __forceinline__ u64 pk2(float lo, float hi) {
    u64 r;
    asm("mov.b64 %0, {%1, %2};" : "=l"(r) : "f"(lo), "f"(hi));
    return r;
}
__device__ __forceinline__ void fma2(u64& d, u64 a, u64 b) {
    asm("fma.rn.f32x2 %0, %1, %2, %0;" : "+l"(d) : "l"(a), "l"(b));
}
__device__ __forceinline__ void unpk2(float& lo, float& hi, u64 v) {
    asm("mov.b64 {%0, %1}, %2;" : "=f"(lo), "=f"(hi) : "l"(v));
}

__global__ void __launch_bounds__(THREADS, 3)
corr_kernel(const __grid_constant__ CUtensorMap tm1,
            const __grid_constant__ CUtensorMap tm2,
            float* __restrict__ out)
{
    __shared__ __align__(128) float s2[NBUF][S2F_PER];  // in2 halo tiles
    __shared__ __align__(128) float s1[NBUF][S1F_PER];  // in1 tiles
    __shared__ __align__(8)   u64   mbar[NBUF];

    const int tid = threadIdx.x;
    const int b   = blockIdx.z;
    const int y0  = blockIdx.y * TY;
    const int x0  = blockIdx.x * TX;

    const uint32_t s2base = (uint32_t)__cvta_generic_to_shared(&s2[0][0]);
    const uint32_t s1base = (uint32_t)__cvta_generic_to_shared(&s1[0][0]);
    const uint32_t mbase  = (uint32_t)__cvta_generic_to_shared(&mbar[0]);

    // ---- compute roles: tid = (yy*9 + dy)*8 + g ----
    const int g   = tid & 7;
    const int dy  = (tid >> 3) % 9;
    const int yy  = tid / 72;

    u64 acc2[PT / 2][P_];
    #pragma unroll
    for (int t = 0; t < PT / 2; t++)
        #pragma unroll
        for (int d = 0; d < P_; d++)
            acc2[t][d] = 0ull;

    const int w_off = (yy + dy) * HALO_W + 4 * g;   // within s2 buffer (floats)
    const int a_off = yy * TX + 4 * g;              // within s1 buffer (floats)

    // ---- init mbarriers ----
    if (tid == 0) {
        #pragma unroll
        for (int i = 0; i < NBUF; i++)
            mbar_init(mbase + 8u * i, 1);
        fence_async_shared();
    }
    __syncthreads();

    // ---- prologue: issue stages 0 and 1 (tid 0 only) ----
    if (tid == 0) {
        #pragma unroll
        for (int ps = 0; ps < 2; ps++) {
            uint32_t mb = mbase + 8u * ps;
            mbar_expect_tx(mb, TX_BYTES);
            tma4d(s1base + ps * S1B_PER, &tm1, x0,     y0,     ps * CC, b, mb);
            tma4d(s2base + ps * S2B_PER, &tm2, x0 - 4, y0 - 4, ps * CC, b, mb);
        }
    }

    #pragma unroll 1
    for (int st = 0; st < NSTAGE; st++) {
        __syncthreads();   // all reads of buffer (st+2)%3 (done at stage st-1)
                           // complete before it is refilled below
        if (tid == 0 && st + 2 < NSTAGE) {
            const int pb = (st + 2) % NBUF;
            uint32_t mb = mbase + 8u * pb;
            mbar_expect_tx(mb, TX_BYTES);
            tma4d(s1base + pb * S1B_PER, &tm1, x0,     y0,     (st + 2) * CC, b, mb);
            tma4d(s2base + pb * S2B_PER, &tm2, x0 - 4, y0 - 4, (st + 2) * CC, b, mb);
        }

        // wait for stage st data
        mbar_wait(mbase + 8u * (st % NBUF), (uint32_t)((st / NBUF) & 1));

        const float* wp = &s2[st % NBUF][w_off];
        const float* ap = &s1[st % NBUF][a_off];

        #pragma unroll 2
        for (int cc = 0; cc < CC; cc++) {
            const float4* wp4 = reinterpret_cast<const float4*>(wp);
            float4 w0 = wp4[0], w1 = wp4[1], w2 = wp4[2];
            float4 a  = *reinterpret_cast<const float4*>(ap);

            u64 av0 = pk2(a.x, a.y);
            u64 av1 = pk2(a.z, a.w);

            float wf[12];
            wf[0] = w0.x; wf[1]  = w0.y; wf[2]  = w0.z; wf[3]  = w0.w;
            wf[4] = w1.x; wf[5]  = w1.y; wf[6]  = w1.z; wf[7]  = w1.w;
            wf[8] = w2.x; wf[9]  = w2.y; wf[10] = w2.z; wf[11] = w2.w;

            u64 wq[11];
            #pragma unroll
            for (int k = 0; k < 11; k++)
                wq[k] = pk2(wf[k], wf[k + 1]);

            #pragma unroll
            for (int d = 0; d < P_; d++) {
                fma2(acc2[0][d], av0, wq[d]);
                fma2(acc2[1][d], av1, wq[d + 2]);
            }

            wp += HALO_H * HALO_W;
            ap += TY * TX;
        }
    }

    // ---- write output: out[b][dy][d][y0+yy][x0+4g .. +3] ----
    {
        const size_t hw = (size_t)HW_;
        float* obase = out + (((size_t)b * P_ + dy) * P_) * hw
                     + (size_t)(y0 + yy) * W_ + x0 + 4 * g;
        #pragma unroll
        for (int d = 0; d < P_; d++) {
            float4 v;
            unpk2(v.x, v.y, acc2[0][d]);
            unpk2(v.z, v.w, acc2[1][d]);
            *reinterpret_cast<float4*>(obase + (size_t)d * hw) = v;
        }
    }
}

// ---- host: resolve cuTensorMapEncodeTiled robustly (no -lcuda needed) ----
typedef CUresult (*EncodeTiledFn)(
    CUtensorMap*, CUtensorMapDataType, cuuint32_t, void*,
    const cuuint64_t*, const cuuint64_t*, const cuuint32_t*, const cuuint32_t*,
    CUtensorMapInterleave, CUtensorMapSwizzle, CUtensorMapL2promotion,
    CUtensorMapFloatOOBfill);

static EncodeTiledFn resolve_encode_fn() {
    void* fn = nullptr;
    // 1) runtime API entry-point query (cudart is always linked)
#if CUDART_VERSION >= 12050
    cudaDriverEntryPointQueryResult qres = cudaDriverEntryPointSuccess;
    if (cudaGetDriverEntryPointByVersion("cuTensorMapEncodeTiled", &fn, 12000,
                                         cudaEnableDefault, &qres) == cudaSuccess
        && qres == cudaDriverEntryPointSuccess && fn)
        return (EncodeTiledFn)fn;
    fn = nullptr;
#endif
    // 2) dlopen libcuda directly
    void* h = dlopen("libcuda.so.1", RTLD_LAZY | RTLD_GLOBAL);
    if (!h) h = dlopen("libcuda.so", RTLD_LAZY | RTLD_GLOBAL);
    if (h) fn = dlsym(h, "cuTensorMapEncodeTiled");
    if (!fn) fn = dlsym(RTLD_DEFAULT, "cuTensorMapEncodeTiled");
    return (EncodeTiledFn)fn;
}

extern "C" void kernel_launch(void* const* d_in, const int* in_sizes, int n_in,
                              void* d_out, int out_size) {
    void* in1 = d_in[0];
    void* in2 = d_in[1];
    float* out = (float*)d_out;

    EncodeTiledFn enc = resolve_encode_fn();
    if (!enc) return;   // cannot proceed (would crash); bench will flag no-work

    cuuint64_t dims[4]    = {W_, H_, C_, B_};
    cuuint64_t strides[3] = {(cuuint64_t)W_ * 4,
                             (cuuint64_t)HW_ * 4,
                             (cuuint64_t)CHW_ * 4};
    cuuint32_t estr[4]    = {1, 1, 1, 1};

    CUtensorMap tm1, tm2;
    cuuint32_t box1[4] = {TX, TY, CC, 1};            // in1 tile
    enc(&tm1, CU_TENSOR_MAP_DATA_TYPE_FLOAT32, 4, in1, dims, strides, box1, estr,
        CU_TENSOR_MAP_INTERLEAVE_NONE, CU_TENSOR_MAP_SWIZZLE_NONE,
        CU_TENSOR_MAP_L2_PROMOTION_L2_128B, CU_TENSOR_MAP_FLOAT_OOB_FILL_NONE);

    cuuint32_t box2[4] = {HALO_W, HALO_H, CC, 1};    // in2 halo (OOB zero-filled)
    enc(&tm2, CU_TENSOR_MAP_DATA_TYPE_FLOAT32, 4, in2, dims, strides, box2, estr,
        CU_TENSOR_MAP_INTERLEAVE_NONE, CU_TENSOR_MAP_SWIZZLE_NONE,
        CU_TENSOR_MAP_L2_PROMOTION_L2_128B, CU_TENSOR_MAP_FLOAT_OOB_FILL_NONE);

    dim3 grid(W_ / TX, H_ / TY, B_);   // (4, 24, 4) = 384 blocks
    dim3 block(THREADS);               // 288
    corr_kernel<<<grid, block>>>(tm1, tm2, out);
}